// round 13
// baseline (speedup 1.0000x reference)
#include <cuda_runtime.h>

// h [B=32, S=16384, D=64] f32; v = h[...,15]*w + b; out[b,s] = cumsum_s(v)/(s+2).
// Single-pass chunked scan with decoupled lookback.
// R13 = R12 (best: 8.19us) + __fdividef as the last untested single variable.
// Config: 1024 blocks x 256 threads x 2 elem/thread (confirmed optimum).
#define B_DIM    32
#define S_DIM    16384
#define D_DIM    64
#define POS      15
#define NCHUNK   32          // chunks per batch row
#define CHUNK    512         // elements per chunk
#define THREADS  256         // 2 elements per thread
#define NSEG     16          // 16 segments of 32 contiguous elements

__device__ unsigned long long g_state[B_DIM * NCHUNK];

__global__ __launch_bounds__(THREADS, 8) void k_fused_scan(
    const float* __restrict__ h,
    const float* __restrict__ w_ptr,
    const float* __restrict__ b_ptr,
    float* __restrict__ out)
{
    const int blk  = blockIdx.x;          // = row*NCHUNK + c
    const int row  = blk >> 5;
    const int c    = blk & (NCHUNK - 1);
    const int t    = threadIdx.x;
    const int lane = t & 31, wid = t >> 5;

    const float w  = *w_ptr;
    const float bv = *b_ptr;

    // Front-batched strided loads: positions t and t+256 of this chunk.
    const size_t base_idx = ((size_t)row * S_DIM + (size_t)c * CHUNK) * D_DIM + POS;
    float x[2];
#pragma unroll
    for (int i = 0; i < 2; i++)
        x[i] = __ldg(h + base_idx + (size_t)(i * 256 + t) * D_DIM);
#pragma unroll
    for (int i = 0; i < 2; i++)
        x[i] = fmaf(x[i], w, bv);

    // Per-warp inclusive scans; segment k = i*8 + wid covers [i*256+wid*32, +32).
    float sc[2];
#pragma unroll
    for (int i = 0; i < 2; i++) {
        float v = x[i];
#pragma unroll
        for (int o = 1; o < 32; o <<= 1) {
            float y = __shfl_up_sync(0xffffffffu, v, o);
            if (lane >= o) v += y;
        }
        sc[i] = v;
    }

    __shared__ float sseg[NSEG];   // segment totals -> inclusive-scanned in place
    __shared__ float s_base;       // exclusive prefix from preceding chunks
#pragma unroll
    for (int i = 0; i < 2; i++)
        if (lane == 31) sseg[i * 8 + wid] = sc[i];
    __syncthreads();

    if (wid == 0) {
        // Inclusive scan of the 16 segment totals in one warp; publish chunk total.
        float v = (lane < NSEG) ? sseg[lane] : 0.0f;
#pragma unroll
        for (int o = 1; o < 32; o <<= 1) {
            float y = __shfl_up_sync(0xffffffffu, v, o);
            if (lane >= o) v += y;
        }
        if (lane < NSEG) sseg[lane] = v;
        if (lane == NSEG - 1) {
            unsigned long long pk =
                (1ULL << 32) | (unsigned long long)__float_as_uint(v);
            atomicExch(&g_state[blk], pk);
        }
    } else if (wid == 1) {
        // Lookback: lanes < c each poll one predecessor chunk of the same row.
        float p = 0.0f;
        if (lane < c) {
            const int idx = (row << 5) + lane;
            unsigned long long st;
            do { st = atomicAdd(&g_state[idx], 0ULL); } while (!(st >> 32));
            p = __uint_as_float((unsigned int)st);
        }
#pragma unroll
        for (int o = 16; o > 0; o >>= 1)
            p += __shfl_xor_sync(0xffffffffu, p, o);
        if (lane == 0) s_base = p;
    }
    __syncthreads();

    const float bb = s_base;
#pragma unroll
    for (int i = 0; i < 2; i++) {
        const int seg  = i * 8 + wid;
        const float ex = (seg > 0) ? sseg[seg - 1] : 0.0f;
        const int s    = c * CHUNK + i * 256 + t;
        out[(size_t)row * S_DIM + s] =
            __fdividef(bb + ex + sc[i], (float)(s + 2));
    }
}

extern "C" void kernel_launch(void* const* d_in, const int* in_sizes, int n_in,
                              void* d_out, int out_size)
{
    const float* h  = (const float*)d_in[0];
    const float* vw = (const float*)d_in[1];
    const float* vb = (const float*)d_in[2];
    float* out = (float*)d_out;

    k_fused_scan<<<B_DIM * NCHUNK, THREADS>>>(h, vw, vb, out);  // 1024 blocks
}

// round 14
// speedup vs baseline: 1.0898x; 1.0898x over previous
#include <cuda_runtime.h>

// h [B=32, S=16384, D=64] f32; v = h[...,15]*w + b; out[b,s] = cumsum_s(v)/(s+2).
// Single-pass chunked scan with decoupled lookback.
// FINAL (= R12, twice-confirmed best: 8.19/8.22us): 1024 blocks x 256 threads x
// 2 elem/thread, single wave, plain __ldg loads. All other levers (cache hints,
// load-path variants, grid/ILP sweep, lookback/div micro-opts) measured and
// rejected; kernel is at the structural floor for this 256B-stride gather.
#define B_DIM    32
#define S_DIM    16384
#define D_DIM    64
#define POS      15
#define NCHUNK   32          // chunks per batch row
#define CHUNK    512         // elements per chunk
#define THREADS  256         // 2 elements per thread
#define NSEG     16          // 16 segments of 32 contiguous elements

__device__ unsigned long long g_state[B_DIM * NCHUNK];

__global__ __launch_bounds__(THREADS, 8) void k_fused_scan(
    const float* __restrict__ h,
    const float* __restrict__ w_ptr,
    const float* __restrict__ b_ptr,
    float* __restrict__ out)
{
    const int blk  = blockIdx.x;          // = row*NCHUNK + c
    const int row  = blk >> 5;
    const int c    = blk & (NCHUNK - 1);
    const int t    = threadIdx.x;
    const int lane = t & 31, wid = t >> 5;

    const float w  = *w_ptr;
    const float bv = *b_ptr;

    // Front-batched strided loads: positions t and t+256 of this chunk.
    const size_t base_idx = ((size_t)row * S_DIM + (size_t)c * CHUNK) * D_DIM + POS;
    float x[2];
#pragma unroll
    for (int i = 0; i < 2; i++)
        x[i] = __ldg(h + base_idx + (size_t)(i * 256 + t) * D_DIM);
#pragma unroll
    for (int i = 0; i < 2; i++)
        x[i] = fmaf(x[i], w, bv);

    // Per-warp inclusive scans; segment k = i*8 + wid covers [i*256+wid*32, +32).
    float sc[2];
#pragma unroll
    for (int i = 0; i < 2; i++) {
        float v = x[i];
#pragma unroll
        for (int o = 1; o < 32; o <<= 1) {
            float y = __shfl_up_sync(0xffffffffu, v, o);
            if (lane >= o) v += y;
        }
        sc[i] = v;
    }

    __shared__ float sseg[NSEG];   // segment totals -> inclusive-scanned in place
    __shared__ float s_base;       // exclusive prefix from preceding chunks
#pragma unroll
    for (int i = 0; i < 2; i++)
        if (lane == 31) sseg[i * 8 + wid] = sc[i];
    __syncthreads();

    if (wid == 0) {
        // Inclusive scan of the 16 segment totals in one warp; publish chunk total.
        float v = (lane < NSEG) ? sseg[lane] : 0.0f;
#pragma unroll
        for (int o = 1; o < 32; o <<= 1) {
            float y = __shfl_up_sync(0xffffffffu, v, o);
            if (lane >= o) v += y;
        }
        if (lane < NSEG) sseg[lane] = v;
        if (lane == NSEG - 1) {
            unsigned long long pk =
                (1ULL << 32) | (unsigned long long)__float_as_uint(v);
            atomicExch(&g_state[blk], pk);
        }
    } else if (wid == 1) {
        // Lookback: lanes < c each poll one predecessor chunk of the same row.
        float p = 0.0f;
        if (lane < c) {
            const int idx = (row << 5) + lane;
            unsigned long long st;
            do { st = atomicAdd(&g_state[idx], 0ULL); } while (!(st >> 32));
            p = __uint_as_float((unsigned int)st);
        }
#pragma unroll
        for (int o = 16; o > 0; o >>= 1)
            p += __shfl_xor_sync(0xffffffffu, p, o);
        if (lane == 0) s_base = p;
    }
    __syncthreads();

    const float bb = s_base;
#pragma unroll
    for (int i = 0; i < 2; i++) {
        const int seg  = i * 8 + wid;
        const float ex = (seg > 0) ? sseg[seg - 1] : 0.0f;
        const int s    = c * CHUNK + i * 256 + t;
        out[(size_t)row * S_DIM + s] = (bb + ex + sc[i]) / (float)(s + 2);
    }
}

extern "C" void kernel_launch(void* const* d_in, const int* in_sizes, int n_in,
                              void* d_out, int out_size)
{
    const float* h  = (const float*)d_in[0];
    const float* vw = (const float*)d_in[1];
    const float* vb = (const float*)d_in[2];
    float* out = (float*)d_out;

    k_fused_scan<<<B_DIM * NCHUNK, THREADS>>>(h, vw, vb, out);  // 1024 blocks
}